// round 9
// baseline (speedup 1.0000x reference)
#include <cuda_runtime.h>
#include <cuda_fp16.h>
#include <cstdint>

#define NPTS      131072
#define DIM       64
#define NCODE     512
#define HWSZ      4096
#define OUT_ELEMS 8388608
#define TILE_M    256
#define NTILES    512
#define TPB       512
#define GRID      148

// ---- smem layout ----
#define OFF_ZT    0              // z tile fp32 [64][256]      65536
#define OFF_A     65536          // A fp16 [256][64] SW128     32768
#define OFF_B     98304          // B fp16 [512][64] SW128     65536
#define OFF_SB3   163840         // 1 + 0.5*||e||^2 [512]       2048
#define OFF_SBF   165888         // ||e||^2 [512]               2048
#define OFF_SAN   167936         // ||z_p||^2 [256]             1024
#define OFF_JB    168960         // int jbest[256]              1024
#define OFF_J2    169984         // int j2nd[256]               1024
#define OFF_FLG   171008         // int flag[256]               1024
#define OFF_CNT   172032         // int count
#define OFF_LIST  172040         // int list[256]
#define OFF_KEY   173064         // u64 argmin key
#define OFF_RED   173072         // double red[16]               128
#define OFF_WMAX  173200         // float wmax[16]                64
#define SMEM_TOTAL 173312

#define SW128(o)  ((o) ^ (((o) >> 3) & 0x70))

__device__ double g_part[GRID];

__device__ __forceinline__ uint32_t smem_u32(const void* p) {
    uint32_t a;
    asm("{ .reg .u64 t; cvta.to.shared.u64 t, %1; cvt.u32.u64 %0, t; }"
        : "=r"(a) : "l"(p));
    return a;
}
#define LDSM4(R, addr)                                                        \
    asm volatile("ldmatrix.sync.aligned.m8n8.x4.shared.b16 {%0,%1,%2,%3}, [%4];" \
                 : "=r"((R)[0]), "=r"((R)[1]), "=r"((R)[2]), "=r"((R)[3])     \
                 : "r"(addr))
#define MMA_FP16(C, A, b0, b1)                                                \
    asm volatile("mma.sync.aligned.m16n8k16.row.col.f32.f16.f16.f32 "        \
                 "{%0,%1,%2,%3},{%4,%5,%6,%7},{%8,%9},{%0,%1,%2,%3};"        \
                 : "+f"((C)[0]), "+f"((C)[1]), "+f"((C)[2]), "+f"((C)[3])     \
                 : "r"((A)[0]), "r"((A)[1]), "r"((A)[2]), "r"((A)[3]),        \
                   "r"(b0), "r"(b1))

// insert x into ascending top-3 K[0]<=K[1]<=K[2] (pure min/max dataflow)
#define INSK(K, x) {                                                          \
    float _mx = fmaxf((x), (K)[0]);                                           \
    (K)[2] = fminf((K)[2], fmaxf(_mx, (K)[1]));                               \
    (K)[1] = fminf((K)[1], _mx);                                              \
    (K)[0] = fminf((K)[0], (x));                                              \
}

// ---------------------------------------------------------------- main
__global__ void __launch_bounds__(TPB, 1)
vq_main(const float* __restrict__ z, const float* __restrict__ emb,
        float* __restrict__ outq) {
    extern __shared__ char smem[];
    const uint32_t sbase = smem_u32(smem);
    float* zt   = (float*)(smem + OFF_ZT);
    float* sB3  = (float*)(smem + OFF_SB3);
    float* sBf  = (float*)(smem + OFF_SBF);
    float* sAn  = (float*)(smem + OFF_SAN);
    int*   jb   = (int*)(smem + OFF_JB);
    int*   j2b  = (int*)(smem + OFF_J2);
    int*   flg  = (int*)(smem + OFF_FLG);
    int*   cnt  = (int*)(smem + OFF_CNT);
    int*   list = (int*)(smem + OFF_LIST);
    unsigned long long* key = (unsigned long long*)(smem + OFF_KEY);
    double* red = (double*)(smem + OFF_RED);
    float* wmax = (float*)(smem + OFF_WMAX);

    const int tid = threadIdx.x, wid = tid >> 5, lane = tid & 31;

    // ---- per-CTA B staging: code j = tid (TPB == NCODE) ----
    {
        const float* er = emb + tid * DIM;
        float s = 0.0f;
#pragma unroll
        for (int c = 0; c < DIM; c += 2) {
            float v0 = er[c], v1 = er[c + 1];
            s = __fadd_rn(s, __fmul_rn(v0, v0));
            s = __fadd_rn(s, __fmul_rn(v1, v1));
            __half2 h2 = __floats2half2_rn(v0, v1);
            *(uint32_t*)(smem + OFF_B + SW128((uint32_t)(tid * 128 + c * 2))) =
                *(uint32_t*)&h2;
        }
        sBf[tid] = s;
        sB3[tid] = __fadd_rn(1.0f, 0.5f * s);
    }
    __syncthreads();

    // Se = max ||e||
    float bmax = sBf[tid];
#pragma unroll
    for (int x = 16; x > 0; x >>= 1)
        bmax = fmaxf(bmax, __shfl_xor_sync(0xffffffffu, bmax, x));
    if (lane == 0) wmax[wid] = bmax;
    __syncthreads();
    float mbv = wmax[0];
#pragma unroll
    for (int w = 1; w < 16; w++) mbv = fmaxf(mbv, wmax[w]);
    const float Se = sqrtf(mbv);

    // ldmatrix lane geometry
    const int mi  = lane >> 3, r8 = lane & 7;
    const int lam = lane & 3,  g  = lane >> 2;
    const uint32_t m0 = wid * 16;
    const uint32_t a_row  = m0 + ((mi & 1) << 3) + r8;
    const uint32_t a_kcol = (mi >> 1) << 3;
    const uint32_t b_crow = ((mi >> 1) << 3) + r8;
    const uint32_t b_kcol = (mi & 1) << 3;

    // B addressing: swizzle mask for this lane is constant (row&7 == r8 for
    // both row groups and all nc since strides are multiples of 8 rows).
    // addr = OFF_B + row*128 + ((col_bytes) ^ (r8*16)); col/row split is exact
    // because col^mask stays < 128.
    const uint32_t bmsk = (uint32_t)(r8 << 4);
    uint32_t colsw[4];
#pragma unroll
    for (int kk = 0; kk < 4; kk++)
        colsw[kk] = ((uint32_t)(kk * 32 + b_kcol * 2)) ^ bmsk;
    const uint32_t brow0 = sbase + OFF_B + b_crow * 128;

    double lacc = 0.0;

    for (int t = blockIdx.x; t < NTILES; t += GRID) {
        const int b   = t >> 4;
        const int hw0 = (t & 15) << 8;
        const float* zsrc = z + ((size_t)b << 18) + hw0;

        __syncthreads();

        // ---- load z tile [64][256] fp32 ----
        for (int f = tid; f < 4096; f += TPB) {
            int row = f >> 6, col = f & 63;
            ((float4*)zt)[f] = ((const float4*)(zsrc + (size_t)row * HWSZ))[col];
        }
        __syncthreads();

        // ---- convert to A fp16 (SW128), per-point norm ----
        if (tid < TILE_M) {
            float A = 0.0f;
#pragma unroll
            for (int c = 0; c < DIM; c += 2) {
                float v0 = zt[c * TILE_M + tid];
                float v1 = zt[(c + 1) * TILE_M + tid];
                A = __fadd_rn(A, __fmul_rn(v0, v0));
                A = __fadd_rn(A, __fmul_rn(v1, v1));
                __half2 hp2 = __floats2half2_rn(v0, v1);
                *(uint32_t*)(smem + OFF_A + SW128((uint32_t)(tid * 128 + c * 2))) =
                    *(uint32_t*)&hp2;
            }
            sAn[tid] = A;
        }
        if (tid == 0) *cnt = 0;
        __syncthreads();

        // ---- A fragments (full SW128 per access — once per tile) ----
        uint32_t Ahi[4][4];
#pragma unroll
        for (int kk = 0; kk < 4; kk++) {
            uint32_t sw = SW128((uint32_t)(a_row * 128 + (kk * 16 + a_kcol) * 2));
            LDSM4(Ahi[kk], sbase + OFF_A + sw);
        }

        // trackers: packed keys (f-value with low 9 mantissa bits = index)
        float Ka0[3] = {3e38f, 3e38f, 3e38f}, Ka1[3] = {3e38f, 3e38f, 3e38f};
        float Kb0[3] = {3e38f, 3e38f, 3e38f}, Kb1[3] = {3e38f, 3e38f, 3e38f};

        uint32_t row0 = brow0;          // nc-dependent row base (+4096/nc)
        const float2* s3f2 = (const float2*)sB3;

#pragma unroll 1
        for (int nc = 0; nc < 16; nc++) {
            const int n0 = nc * 32;
            float2 w0 = s3f2[(n0 >> 1) + 0 + lam];
            float2 w1 = s3f2[(n0 >> 1) + 4 + lam];
            float2 w2 = s3f2[(n0 >> 1) + 8 + lam];
            float2 w3 = s3f2[(n0 >> 1) + 12 + lam];

            float C[4][4];
#pragma unroll
            for (int nt = 0; nt < 4; nt++)
#pragma unroll
                for (int u = 0; u < 4; u++) C[nt][u] = 0.0f;

#pragma unroll
            for (int kk = 0; kk < 4; kk++) {
                uint32_t bh[8];
                LDSM4(bh + 0, row0 + colsw[kk]);
                LDSM4(bh + 4, row0 + 2048 + colsw[kk]);
#pragma unroll
                for (int nt = 0; nt < 4; nt++)
                    MMA_FP16(C[nt], Ahi[kk], bh[nt * 2], bh[nt * 2 + 1]);
            }
            row0 += 4096;

            // epilogue: packed keys, 4 parallel tracker sets
            const int jcb = n0 + (lam << 1);
#pragma unroll
            for (int nt = 0; nt < 4; nt++) {
                float2 w = (nt == 0) ? w0 : (nt == 1) ? w1 : (nt == 2) ? w2 : w3;
                int jc = jcb + nt * 8;
                float f00 = __fadd_rn(w.x, -C[nt][0]);
                float f01 = __fadd_rn(w.y, -C[nt][1]);
                float f10 = __fadd_rn(w.x, -C[nt][2]);
                float f11 = __fadd_rn(w.y, -C[nt][3]);
                float x00 = __uint_as_float((__float_as_uint(f00) & 0xFFFFFE00u) | (uint32_t)jc);
                float x01 = __uint_as_float((__float_as_uint(f01) & 0xFFFFFE00u) | (uint32_t)(jc + 1));
                float x10 = __uint_as_float((__float_as_uint(f10) & 0xFFFFFE00u) | (uint32_t)jc);
                float x11 = __uint_as_float((__float_as_uint(f11) & 0xFFFFFE00u) | (uint32_t)(jc + 1));
                if (nt < 2) {
                    INSK(Ka0, x00) INSK(Ka0, x01)
                    INSK(Kb0, x10) INSK(Kb0, x11)
                } else {
                    INSK(Ka1, x00) INSK(Ka1, x01)
                    INSK(Kb1, x10) INSK(Kb1, x11)
                }
            }
        }

        // merge set1 into set0
        INSK(Ka0, Ka1[0]) INSK(Ka0, Ka1[1]) INSK(Ka0, Ka1[2])
        INSK(Kb0, Kb1[0]) INSK(Kb0, Kb1[1]) INSK(Kb0, Kb1[2])

        // quad merge (lanes sharing rows)
#pragma unroll
        for (int x = 1; x < 4; x <<= 1) {
            float q1 = __shfl_xor_sync(0xffffffffu, Ka0[0], x);
            float q2 = __shfl_xor_sync(0xffffffffu, Ka0[1], x);
            float q3 = __shfl_xor_sync(0xffffffffu, Ka0[2], x);
            INSK(Ka0, q1) INSK(Ka0, q2) INSK(Ka0, q3)
            q1 = __shfl_xor_sync(0xffffffffu, Kb0[0], x);
            q2 = __shfl_xor_sync(0xffffffffu, Kb0[1], x);
            q3 = __shfl_xor_sync(0xffffffffu, Kb0[2], x);
            INSK(Kb0, q1) INSK(Kb0, q2) INSK(Kb0, q3)
        }

        if (lam == 0) {
            int p0 = m0 + g, p1 = m0 + g + 8;
            float th0 = __fmaf_rn(0.00204f * sqrtf(sAn[p0]), Se, 1.4e-4f);
            float th1 = __fmaf_rn(0.00204f * sqrtf(sAn[p1]), Se, 1.4e-4f);
            jb[p0]  = (int)(__float_as_uint(Ka0[0]) & 511u);
            j2b[p0] = (int)(__float_as_uint(Ka0[1]) & 511u);
            jb[p1]  = (int)(__float_as_uint(Kb0[0]) & 511u);
            j2b[p1] = (int)(__float_as_uint(Kb0[1]) & 511u);
            flg[p0] = (Ka0[2] - Ka0[0]) <= th0 ? 2 : ((Ka0[1] - Ka0[0]) <= th0 ? 1 : 0);
            flg[p1] = (Kb0[2] - Kb0[0]) <= th1 ? 2 : ((Kb0[1] - Kb0[0]) <= th1 ? 1 : 0);
        }
        __syncthreads();

        // ---- full exact fallback (flag==2, very rare): CTA-cooperative ----
        if (tid < TILE_M && flg[tid] == 2) { int pos = atomicAdd(cnt, 1); list[pos] = tid; }
        __syncthreads();
        const int nf = *cnt;
        for (int i = 0; i < nf; i++) {
            int p = list[i];
            if (tid == 0) *key = ~0ull;
            __syncthreads();
            float Ap = sAn[p];
            {
                int j = tid;   // TPB == NCODE
                const float* e = emb + j * DIM;
                float Cx = 0.0f;
#pragma unroll
                for (int c = 0; c < DIM; c++)
                    Cx = __fmaf_rn(zt[c * TILE_M + p], __ldg(e + c), Cx);
                float tt = __fadd_rn(Ap, sBf[j]);
                float dd = __fadd_rn(tt, -2.0f * Cx);
                unsigned du = __float_as_uint(dd);
                unsigned od = (du & 0x80000000u) ? ~du : (du ^ 0x80000000u);
                atomicMin(key, ((unsigned long long)od << 32) | (unsigned)j);
            }
            __syncthreads();
            if (tid == 0) jb[p] = (int)(*key & 0xffffffffu);
            __syncthreads();
        }

        // ---- 2-candidate exact refine (flag==1) + output + loss ----
        if (tid < TILE_M) {
            int jq = jb[tid];
            if (flg[tid] == 1) {
                int ja = jq, jc2 = j2b[tid];
                int lo = ja < jc2 ? ja : jc2;
                int hi = ja < jc2 ? jc2 : ja;
                float Ap = sAn[tid];
                float Cl = 0.0f, Ch = 0.0f;
                const float* el = emb + lo * DIM;
                const float* eh = emb + hi * DIM;
#pragma unroll
                for (int c = 0; c < DIM; c++) {
                    float zv = zt[c * TILE_M + tid];
                    Cl = __fmaf_rn(zv, __ldg(el + c), Cl);
                    Ch = __fmaf_rn(zv, __ldg(eh + c), Ch);
                }
                float dl = __fadd_rn(__fadd_rn(Ap, sBf[lo]), -2.0f * Cl);
                float dh = __fadd_rn(__fadd_rn(Ap, sBf[hi]), -2.0f * Ch);
                jq = (dh < dl) ? hi : lo;   // ties -> lower index
            }
            const float4* er4 = (const float4*)(emb + jq * DIM);
            float* obase = outq + ((size_t)b << 18) + hw0 + tid;
#pragma unroll
            for (int c4 = 0; c4 < 16; c4++) {
                float4 q = __ldg(er4 + c4);
                int c = c4 * 4;
                obase[(size_t)(c + 0) * HWSZ] = q.x;
                obase[(size_t)(c + 1) * HWSZ] = q.y;
                obase[(size_t)(c + 2) * HWSZ] = q.z;
                obase[(size_t)(c + 3) * HWSZ] = q.w;
                float e0 = __fadd_rn(q.x, -zt[(c + 0) * TILE_M + tid]);
                float e1 = __fadd_rn(q.y, -zt[(c + 1) * TILE_M + tid]);
                float e2 = __fadd_rn(q.z, -zt[(c + 2) * TILE_M + tid]);
                float e3 = __fadd_rn(q.w, -zt[(c + 3) * TILE_M + tid]);
                lacc += (double)__fmul_rn(e0, e0);
                lacc += (double)__fmul_rn(e1, e1);
                lacc += (double)__fmul_rn(e2, e2);
                lacc += (double)__fmul_rn(e3, e3);
            }
        }
    }

    // ---- deterministic loss reduction ----
    __syncthreads();
#pragma unroll
    for (int off = 16; off > 0; off >>= 1)
        lacc += __shfl_down_sync(0xffffffffu, lacc, off);
    if (lane == 0) red[wid] = lacc;
    __syncthreads();
    if (tid == 0) {
        double s = 0.0;
        for (int w = 0; w < 16; w++) s += red[w];
        g_part[blockIdx.x] = s;
    }
}

// ---------------------------------------------------------------- finalize
__global__ void vq_finalize(float* __restrict__ loss_out) {
    double s = 0.0;
    for (int i = 0; i < GRID; i++) s += g_part[i];
    float m = (float)(s / (double)OUT_ELEMS);
    loss_out[0] = __fadd_rn(m, __fmul_rn(0.25f, m));
}

// ----------------------------------------------------------------
extern "C" void kernel_launch(void* const* d_in, const int* in_sizes, int n_in,
                              void* d_out, int out_size) {
    const float* z   = (const float*)d_in[0];
    const float* emb = (const float*)d_in[1];
    if (n_in >= 2 && in_sizes[0] == NCODE * DIM && in_sizes[1] == OUT_ELEMS) {
        const float* t = z; z = emb; emb = t;
    }

    float* out   = (float*)d_out;
    float* loss  = nullptr;
    float* qbase = out;
    if (out_size > OUT_ELEMS) { loss = out; qbase = out + 1; }

    cudaFuncSetAttribute(vq_main, cudaFuncAttributeMaxDynamicSharedMemorySize,
                         SMEM_TOTAL);

    vq_main<<<GRID, TPB, SMEM_TOTAL>>>(z, emb, qbase);
    if (loss) vq_finalize<<<1, 1>>>(loss);
}

// round 10
// speedup vs baseline: 2.2118x; 2.2118x over previous
#include <cuda_runtime.h>
#include <cuda_fp16.h>
#include <cstdint>

#define NPTS      131072
#define DIM       64
#define NCODE     512
#define HWSZ      4096
#define OUT_ELEMS 8388608
#define TILE_M    256
#define NTILES    512
#define TPB       512
#define GRID      148

// ---- smem layout ----
#define OFF_ZT    0              // z tile fp32 [64][256]      65536
#define OFF_AHI   65536          // A_hi fp16 [256][64] SW128  32768
#define OFF_ALO   98304          // A_lo fp16 [256][64] SW128  32768
#define OFF_B     131072         // B eh fp16 [512][64] SW128  65536
#define OFF_SB3   196608         // 1 + 0.5*||e||^2 [512]       2048
#define OFF_SBF   198656         // ||e||^2 [512]               2048
#define OFF_SAN   200704         // ||z_p||^2 [256]             1024
#define OFF_JB    201728         // int j1[256]
#define OFF_J2    202752         // int j2[256]
#define OFF_J3    203776         // int j3[256]
#define OFF_FLG   204800         // int flag[256]
#define OFF_CNT   205824
#define OFF_LIST  205832
#define OFF_KEY   206856
#define OFF_RED   206864
#define OFF_WMAX  206992
#define SMEM_TOTAL 207104

#define SW128(o)  ((o) ^ (((o) >> 3) & 0x70))

__device__ double g_part[GRID];

__device__ __forceinline__ uint32_t smem_u32(const void* p) {
    uint32_t a;
    asm("{ .reg .u64 t; cvta.to.shared.u64 t, %1; cvt.u32.u64 %0, t; }"
        : "=r"(a) : "l"(p));
    return a;
}
#define LDSM4(R, addr)                                                        \
    asm volatile("ldmatrix.sync.aligned.m8n8.x4.shared.b16 {%0,%1,%2,%3}, [%4];" \
                 : "=r"((R)[0]), "=r"((R)[1]), "=r"((R)[2]), "=r"((R)[3])     \
                 : "r"(addr))
#define MMA_FP16(C, A, b0, b1)                                                \
    asm volatile("mma.sync.aligned.m16n8k16.row.col.f32.f16.f16.f32 "        \
                 "{%0,%1,%2,%3},{%4,%5,%6,%7},{%8,%9},{%0,%1,%2,%3};"        \
                 : "+f"((C)[0]), "+f"((C)[1]), "+f"((C)[2]), "+f"((C)[3])     \
                 : "r"((A)[0]), "r"((A)[1]), "r"((A)[2]), "r"((A)[3]),        \
                   "r"(b0), "r"(b1))

// branchless insert of (x,jx) into ascending top-4 (v4 value-only).
// strict < : ties keep earlier-inserted (lower j within a lane); cross-lane
// ties always flag (gap 0 <= th) and are resolved by the exact refine.
#define INS4(v1, v2, v3, v4, j1, j2, j3, x, jx) {                             \
    bool  _p1 = (x) < (v1);                                                   \
    float _t2 = _p1 ? (v1) : (x); int _u2 = _p1 ? (j1) : (jx);                \
    (v1) = fminf((v1), (x));      (j1) = _p1 ? (jx) : (j1);                   \
    bool  _q2 = _t2 < (v2);                                                   \
    float _t3 = _q2 ? (v2) : _t2; int _u3 = _q2 ? (j2) : _u2;                 \
    (v2) = fminf((v2), _t2);      (j2) = _q2 ? _u2 : (j2);                    \
    bool  _q3 = _t3 < (v3);                                                   \
    float _t4 = _q3 ? (v3) : _t3;                                             \
    (v3) = fminf((v3), _t3);      (j3) = _q3 ? _u3 : (j3);                    \
    (v4) = fminf((v4), _t4);                                                  \
}

// ---------------------------------------------------------------- main
__global__ void __launch_bounds__(TPB, 1)
vq_main(const float* __restrict__ z, const float* __restrict__ emb,
        float* __restrict__ outq) {
    extern __shared__ char smem[];
    const uint32_t sbase = smem_u32(smem);
    float* zt   = (float*)(smem + OFF_ZT);
    float* sB3  = (float*)(smem + OFF_SB3);
    float* sBf  = (float*)(smem + OFF_SBF);
    float* sAn  = (float*)(smem + OFF_SAN);
    int*   jb1  = (int*)(smem + OFF_JB);
    int*   jb2  = (int*)(smem + OFF_J2);
    int*   jb3  = (int*)(smem + OFF_J3);
    int*   flg  = (int*)(smem + OFF_FLG);
    int*   cnt  = (int*)(smem + OFF_CNT);
    int*   list = (int*)(smem + OFF_LIST);
    unsigned long long* key = (unsigned long long*)(smem + OFF_KEY);
    double* red = (double*)(smem + OFF_RED);
    float* wmax = (float*)(smem + OFF_WMAX);

    const int tid = threadIdx.x, wid = tid >> 5, lane = tid & 31;

    // ---- B staging: code j = tid (TPB == NCODE); eh only ----
    {
        const float* er = emb + tid * DIM;
        float s = 0.0f;
#pragma unroll
        for (int c = 0; c < DIM; c += 2) {
            float v0 = er[c], v1 = er[c + 1];
            s = __fadd_rn(s, __fmul_rn(v0, v0));
            s = __fadd_rn(s, __fmul_rn(v1, v1));
            __half2 h2 = __floats2half2_rn(v0, v1);
            *(uint32_t*)(smem + OFF_B + SW128((uint32_t)(tid * 128 + c * 2))) =
                *(uint32_t*)&h2;
        }
        sBf[tid] = s;
        sB3[tid] = __fadd_rn(1.0f, 0.5f * s);
    }
    __syncthreads();

    // Se = max ||e||
    float bmax = sBf[tid];
#pragma unroll
    for (int x = 16; x > 0; x >>= 1)
        bmax = fmaxf(bmax, __shfl_xor_sync(0xffffffffu, bmax, x));
    if (lane == 0) wmax[wid] = bmax;
    __syncthreads();
    float mbv = wmax[0];
#pragma unroll
    for (int w = 1; w < 16; w++) mbv = fmaxf(mbv, wmax[w]);
    const float Se = sqrtf(mbv);

    // ldmatrix lane geometry
    const int mi  = lane >> 3, r8 = lane & 7;
    const int lam = lane & 3,  g  = lane >> 2;
    const uint32_t m0 = wid * 16;
    const uint32_t a_row  = m0 + ((mi & 1) << 3) + r8;
    const uint32_t a_kcol = (mi >> 1) << 3;
    const uint32_t b_crow = ((mi >> 1) << 3) + r8;
    const uint32_t b_kcol = (mi & 1) << 3;

    // B swizzle: mask constant per lane (row&7 == r8 always); col^mask < 128
    const uint32_t bmsk = (uint32_t)(r8 << 4);
    uint32_t colsw[4];
#pragma unroll
    for (int kk = 0; kk < 4; kk++)
        colsw[kk] = ((uint32_t)(kk * 32 + b_kcol * 2)) ^ bmsk;
    const uint32_t brow0 = sbase + OFF_B + b_crow * 128;

    double lacc = 0.0;

    for (int t = blockIdx.x; t < NTILES; t += GRID) {
        const int b   = t >> 4;
        const int hw0 = (t & 15) << 8;
        const float* zsrc = z + ((size_t)b << 18) + hw0;

        __syncthreads();

        // ---- load z tile [64][256] fp32 ----
        for (int f = tid; f < 4096; f += TPB) {
            int row = f >> 6, col = f & 63;
            ((float4*)zt)[f] = ((const float4*)(zsrc + (size_t)row * HWSZ))[col];
        }
        __syncthreads();

        // ---- convert to A_hi/A_lo fp16 (SW128), per-point norm ----
        if (tid < TILE_M) {
            float A = 0.0f;
#pragma unroll
            for (int c = 0; c < DIM; c += 2) {
                float v0 = zt[c * TILE_M + tid];
                float v1 = zt[(c + 1) * TILE_M + tid];
                A = __fadd_rn(A, __fmul_rn(v0, v0));
                A = __fadd_rn(A, __fmul_rn(v1, v1));
                __half h0 = __float2half_rn(v0);
                __half h1 = __float2half_rn(v1);
                __half l0 = __float2half_rn(v0 - __half2float(h0));
                __half l1 = __float2half_rn(v1 - __half2float(h1));
                uint32_t hp = (uint32_t)__half_as_ushort(h0) |
                              ((uint32_t)__half_as_ushort(h1) << 16);
                uint32_t lp = (uint32_t)__half_as_ushort(l0) |
                              ((uint32_t)__half_as_ushort(l1) << 16);
                uint32_t sw = SW128((uint32_t)(tid * 128 + c * 2));
                *(uint32_t*)(smem + OFF_AHI + sw) = hp;
                *(uint32_t*)(smem + OFF_ALO + sw) = lp;
            }
            sAn[tid] = A;
        }
        if (tid == 0) *cnt = 0;
        __syncthreads();

        // ---- A fragments ----
        uint32_t Ahi[4][4], Alo[4][4];
#pragma unroll
        for (int kk = 0; kk < 4; kk++) {
            uint32_t sw = SW128((uint32_t)(a_row * 128 + (kk * 16 + a_kcol) * 2));
            LDSM4(Ahi[kk], sbase + OFF_AHI + sw);
            LDSM4(Alo[kk], sbase + OFF_ALO + sw);
        }

        // trackers: ascending minima, rows a (g) and b (g+8)
        float va1 = 3e38f, va2 = 3e38f, va3 = 3e38f, va4 = 3e38f;
        float vb1 = 3e38f, vb2 = 3e38f, vb3 = 3e38f, vb4 = 3e38f;
        int ja1 = 0, ja2 = 0, ja3 = 0, jx1 = 0, jx2 = 0, jx3 = 0;

        uint32_t row0 = brow0;
        const float2* s3f2 = (const float2*)sB3;

#pragma unroll 1
        for (int nc = 0; nc < 16; nc++) {
            const int n0 = nc * 32;
            float2 w0 = s3f2[(n0 >> 1) + 0 + lam];
            float2 w1 = s3f2[(n0 >> 1) + 4 + lam];
            float2 w2 = s3f2[(n0 >> 1) + 8 + lam];
            float2 w3 = s3f2[(n0 >> 1) + 12 + lam];

            float C[4][4];
#pragma unroll
            for (int nt = 0; nt < 4; nt++)
#pragma unroll
                for (int u = 0; u < 4; u++) C[nt][u] = 0.0f;

#pragma unroll
            for (int kk = 0; kk < 4; kk++) {
                uint32_t bh[8];
                LDSM4(bh + 0, row0 + colsw[kk]);
                LDSM4(bh + 4, row0 + 2048 + colsw[kk]);
#pragma unroll
                for (int nt = 0; nt < 4; nt++)
                    MMA_FP16(C[nt], Ahi[kk], bh[nt * 2], bh[nt * 2 + 1]);
#pragma unroll
                for (int nt = 0; nt < 4; nt++)
                    MMA_FP16(C[nt], Alo[kk], bh[nt * 2], bh[nt * 2 + 1]);
            }
            row0 += 4096;

            // epilogue: f = (1 + B/2) - C, insert into top-4
            const int jcb = n0 + (lam << 1);
#pragma unroll
            for (int nt = 0; nt < 4; nt++) {
                float2 w = (nt == 0) ? w0 : (nt == 1) ? w1 : (nt == 2) ? w2 : w3;
                int jc = jcb + nt * 8;
                float f00 = __fadd_rn(w.x, -C[nt][0]);
                float f01 = __fadd_rn(w.y, -C[nt][1]);
                float f10 = __fadd_rn(w.x, -C[nt][2]);
                float f11 = __fadd_rn(w.y, -C[nt][3]);
                INS4(va1, va2, va3, va4, ja1, ja2, ja3, f00, jc)
                INS4(va1, va2, va3, va4, ja1, ja2, ja3, f01, jc + 1)
                INS4(vb1, vb2, vb3, vb4, jx1, jx2, jx3, f10, jc)
                INS4(vb1, vb2, vb3, vb4, jx1, jx2, jx3, f11, jc + 1)
            }
        }

        // quad merge (lanes sharing rows)
#pragma unroll
        for (int x = 1; x < 4; x <<= 1) {
            float w1 = __shfl_xor_sync(0xffffffffu, va1, x);
            float w2 = __shfl_xor_sync(0xffffffffu, va2, x);
            float w3 = __shfl_xor_sync(0xffffffffu, va3, x);
            float w4 = __shfl_xor_sync(0xffffffffu, va4, x);
            int   k1 = __shfl_xor_sync(0xffffffffu, ja1, x);
            int   k2 = __shfl_xor_sync(0xffffffffu, ja2, x);
            int   k3 = __shfl_xor_sync(0xffffffffu, ja3, x);
            INS4(va1, va2, va3, va4, ja1, ja2, ja3, w1, k1)
            INS4(va1, va2, va3, va4, ja1, ja2, ja3, w2, k2)
            INS4(va1, va2, va3, va4, ja1, ja2, ja3, w3, k3)
            va4 = fminf(va4, w4);
            w1 = __shfl_xor_sync(0xffffffffu, vb1, x);
            w2 = __shfl_xor_sync(0xffffffffu, vb2, x);
            w3 = __shfl_xor_sync(0xffffffffu, vb3, x);
            w4 = __shfl_xor_sync(0xffffffffu, vb4, x);
            k1 = __shfl_xor_sync(0xffffffffu, jx1, x);
            k2 = __shfl_xor_sync(0xffffffffu, jx2, x);
            k3 = __shfl_xor_sync(0xffffffffu, jx3, x);
            INS4(vb1, vb2, vb3, vb4, jx1, jx2, jx3, w1, k1)
            INS4(vb1, vb2, vb3, vb4, jx1, jx2, jx3, w2, k2)
            INS4(vb1, vb2, vb3, vb4, jx1, jx2, jx3, w3, k3)
            vb4 = fminf(vb4, w4);
        }

        if (lam == 0) {
            int p0 = m0 + g, p1 = m0 + g + 8;
            float th0 = __fmaf_rn(0.000977f * sqrtf(sAn[p0]), Se, 2.5e-5f);
            float th1 = __fmaf_rn(0.000977f * sqrtf(sAn[p1]), Se, 2.5e-5f);
            jb1[p0] = ja1; jb2[p0] = ja2; jb3[p0] = ja3;
            jb1[p1] = jx1; jb2[p1] = jx2; jb3[p1] = jx3;
            flg[p0] = (va4 - va1) <= th0 ? 7 :
                      ((va3 - va1) <= th0 ? 3 : ((va2 - va1) <= th0 ? 1 : 0));
            flg[p1] = (vb4 - vb1) <= th1 ? 7 :
                      ((vb3 - vb1) <= th1 ? 3 : ((vb2 - vb1) <= th1 ? 1 : 0));
        }
        __syncthreads();

        // ---- full exact fallback (flag==7, rare): CTA-cooperative ----
        if (tid < TILE_M && flg[tid] == 7) { int pos = atomicAdd(cnt, 1); list[pos] = tid; }
        __syncthreads();
        const int nf = *cnt;
        for (int i = 0; i < nf; i++) {
            int p = list[i];
            if (tid == 0) *key = ~0ull;
            __syncthreads();
            float Ap = sAn[p];
            {
                int j = tid;   // TPB == NCODE
                const float* e = emb + j * DIM;
                float Cx = 0.0f;
#pragma unroll
                for (int c = 0; c < DIM; c++)
                    Cx = __fmaf_rn(zt[c * TILE_M + p], __ldg(e + c), Cx);
                float tt = __fadd_rn(Ap, sBf[j]);
                float dd = __fadd_rn(tt, -2.0f * Cx);
                unsigned du = __float_as_uint(dd);
                unsigned od = (du & 0x80000000u) ? ~du : (du ^ 0x80000000u);
                atomicMin(key, ((unsigned long long)od << 32) | (unsigned)j);
            }
            __syncthreads();
            if (tid == 0) jb1[p] = (int)(*key & 0xffffffffu);
            __syncthreads();
        }

        // ---- exact refine (flag 1/3) + output + loss ----
        if (tid < TILE_M) {
            int fl_ = flg[tid];
            int jq  = jb1[tid];
            if (fl_ == 1 || fl_ == 3) {
                int c2 = jb2[tid];
                float Ap = sAn[tid];
                const float* e1p = emb + jq * DIM;
                const float* e2p = emb + c2 * DIM;
                float C1 = 0.0f, C2 = 0.0f;
#pragma unroll
                for (int c = 0; c < DIM; c++) {
                    float zv = zt[c * TILE_M + tid];
                    C1 = __fmaf_rn(zv, __ldg(e1p + c), C1);
                    C2 = __fmaf_rn(zv, __ldg(e2p + c), C2);
                }
                float d1 = __fadd_rn(__fadd_rn(Ap, sBf[jq]), -2.0f * C1);
                float d2 = __fadd_rn(__fadd_rn(Ap, sBf[c2]), -2.0f * C2);
                int   bj = jq; float bd = d1;
                if (d2 < bd || (d2 == bd && c2 < bj)) { bd = d2; bj = c2; }
                if (fl_ == 3) {
                    int c3 = jb3[tid];
                    const float* e3p = emb + c3 * DIM;
                    float C3 = 0.0f;
#pragma unroll
                    for (int c = 0; c < DIM; c++)
                        C3 = __fmaf_rn(zt[c * TILE_M + tid], __ldg(e3p + c), C3);
                    float d3 = __fadd_rn(__fadd_rn(Ap, sBf[c3]), -2.0f * C3);
                    if (d3 < bd || (d3 == bd && c3 < bj)) { bd = d3; bj = c3; }
                }
                jq = bj;
            }
            const float4* er4 = (const float4*)(emb + jq * DIM);
            float* obase = outq + ((size_t)b << 18) + hw0 + tid;
#pragma unroll
            for (int c4 = 0; c4 < 16; c4++) {
                float4 q = __ldg(er4 + c4);
                int c = c4 * 4;
                obase[(size_t)(c + 0) * HWSZ] = q.x;
                obase[(size_t)(c + 1) * HWSZ] = q.y;
                obase[(size_t)(c + 2) * HWSZ] = q.z;
                obase[(size_t)(c + 3) * HWSZ] = q.w;
                float e0 = __fadd_rn(q.x, -zt[(c + 0) * TILE_M + tid]);
                float e1 = __fadd_rn(q.y, -zt[(c + 1) * TILE_M + tid]);
                float e2 = __fadd_rn(q.z, -zt[(c + 2) * TILE_M + tid]);
                float e3 = __fadd_rn(q.w, -zt[(c + 3) * TILE_M + tid]);
                lacc += (double)__fmul_rn(e0, e0);
                lacc += (double)__fmul_rn(e1, e1);
                lacc += (double)__fmul_rn(e2, e2);
                lacc += (double)__fmul_rn(e3, e3);
            }
        }
    }

    // ---- deterministic loss reduction ----
    __syncthreads();
#pragma unroll
    for (int off = 16; off > 0; off >>= 1)
        lacc += __shfl_down_sync(0xffffffffu, lacc, off);
    if (lane == 0) red[wid] = lacc;
    __syncthreads();
    if (tid == 0) {
        double s = 0.0;
        for (int w = 0; w < 16; w++) s += red[w];
        g_part[blockIdx.x] = s;
    }
}

// ---------------------------------------------------------------- finalize
__global__ void vq_finalize(float* __restrict__ loss_out) {
    double s = 0.0;
    for (int i = 0; i < GRID; i++) s += g_part[i];
    float m = (float)(s / (double)OUT_ELEMS);
    loss_out[0] = __fadd_rn(m, __fmul_rn(0.25f, m));
}

// ----------------------------------------------------------------
extern "C" void kernel_launch(void* const* d_in, const int* in_sizes, int n_in,
                              void* d_out, int out_size) {
    const float* z   = (const float*)d_in[0];
    const float* emb = (const float*)d_in[1];
    if (n_in >= 2 && in_sizes[0] == NCODE * DIM && in_sizes[1] == OUT_ELEMS) {
        const float* t = z; z = emb; emb = t;
    }

    float* out   = (float*)d_out;
    float* loss  = nullptr;
    float* qbase = out;
    if (out_size > OUT_ELEMS) { loss = out; qbase = out + 1; }

    cudaFuncSetAttribute(vq_main, cudaFuncAttributeMaxDynamicSharedMemorySize,
                         SMEM_TOTAL);

    vq_main<<<GRID, TPB, SMEM_TOTAL>>>(z, emb, qbase);
    if (loss) vq_finalize<<<1, 1>>>(loss);
}